// round 6
// baseline (speedup 1.0000x reference)
#include <cuda_runtime.h>
#include <math.h>

#define HWSZ 25600        // 160*160
#define IMG  614400       // 24*HWSZ  (per-channel size in [B,C,D,H,W])
#define BST  19660800     // 32*IMG   (per-batch stride for C=32 tensors)
#define HBUF 3276800      // 4 images * 32ch * HWSZ (fwd b0,b1 + bwd b0,b1)

typedef unsigned long long u64;

// packed fp32x2 helpers (sm_103a FFMA2 path — only reachable via PTX)
__device__ __forceinline__ u64 pack2(float lo, float hi){
    u64 r; asm("mov.b64 %0, {%1,%2};" : "=l"(r) : "f"(lo), "f"(hi)); return r;
}
__device__ __forceinline__ void unpack2(u64 v, float& lo, float& hi){
    asm("mov.b64 {%0,%1}, %2;" : "=f"(lo), "=f"(hi) : "l"(v));
}
__device__ __forceinline__ u64 fma2(u64 a, u64 b, u64 c){
    u64 d; asm("fma.rn.f32x2 %0, %1, %2, %3;" : "=l"(d) : "l"(a), "l"(b), "l"(c));
    return d;
}

// ---------------- scratch (device globals; no allocations) ----------------
__device__ float g_sf1[78643200];        // [2,64,24,160,160]  slice_flow mid
__device__ float g_pre[3][39321600];     // Ux, Rx, Ox  (x-layout [B,C,D,H,W])
__device__ float g_h[2][HBUF];           // ping-pong hidden state, 4 images
__device__ float g_u[HBUF];              // update gate
__device__ float g_rh[HBUF];             // reset*h
__device__ float g_gn[32];               // [b][group][sum,sumsq]
__device__ float g_A[128];               // GN affine scale  [b][64]
__device__ float g_B[128];               // GN affine shift

__device__ __forceinline__ float sigm(float z){ return 1.0f/(1.0f+expf(-z)); }

// ---------------- zero the GN accumulator ----------------
__global__ void k_gz(){ if (threadIdx.x < 32) g_gn[threadIdx.x] = 0.f; }

// ---------------- f1: conv3d over D (32->64) + bias + GN partial sums ----------------
// grid (100 hw-tiles, 48 images=(b,d)), 256 threads = 32 lanes x 8 oc-groups(8oc)
__global__ void __launch_bounds__(256) k_f1(const float* __restrict__ x,
                                            const float* __restrict__ w,
                                            const float* __restrict__ b)
{
    __shared__ float ws[6144];                       // [64oc][32ic][3t]
    int tid = threadIdx.x;
    #pragma unroll 1
    for (int i = tid; i < 6144; i += 256) ws[i] = w[i];
    __syncthreads();

    int n  = blockIdx.y; int bb = n / 24, d = n - bb*24;
    int lane = tid & 31, ocg = tid >> 5;             // ocg == GN group
    int hw0 = blockIdx.x * 256 + lane;

    float acc[8][8];
    #pragma unroll
    for (int j=0;j<8;j++){
        #pragma unroll
        for (int k=0;k<8;k++) acc[j][k]=0.f;
    }
    const float* xb = x + bb*BST;

    #pragma unroll 1
    for (int ic = 0; ic < 32; ic++) {
        float wr[8][3];
        #pragma unroll
        for (int j=0;j<8;j++){
            int oc = ocg*8+j;
            wr[j][0]=ws[oc*96+ic*3+0];
            wr[j][1]=ws[oc*96+ic*3+1];
            wr[j][2]=ws[oc*96+ic*3+2];
        }
        #pragma unroll
        for (int t=0;t<3;t++){
            int dd = d + t - 1;
            if (dd >= 0 && dd < 24){
                const float* xp = xb + ic*IMG + dd*HWSZ + hw0;
                #pragma unroll
                for (int k=0;k<8;k++){
                    float v = __ldg(xp + k*32);
                    #pragma unroll
                    for (int j=0;j<8;j++) acc[j][k] = fmaf(wr[j][t], v, acc[j][k]);
                }
            }
        }
    }

    float s=0.f, ss=0.f;
    #pragma unroll
    for (int j=0;j<8;j++){
        int oc = ocg*8+j;
        float bv = b[oc];
        float* op = g_sf1 + (bb*64+oc)*IMG + d*HWSZ + hw0;
        #pragma unroll
        for (int k=0;k<8;k++){
            float v = acc[j][k] + bv;
            op[k*32] = v;
            s += v; ss = fmaf(v,v,ss);
        }
    }
    // all 32 lanes of this warp belong to the same (b, group)
    #pragma unroll
    for (int o=16;o;o>>=1){
        s  += __shfl_xor_sync(0xffffffffu, s,  o);
        ss += __shfl_xor_sync(0xffffffffu, ss, o);
    }
    if (lane == 0){
        atomicAdd(&g_gn[(bb*8+ocg)*2+0], s);
        atomicAdd(&g_gn[(bb*8+ocg)*2+1], ss);
    }
}

// ---------------- GN finalize: per (b,channel) affine ----------------
__global__ void k_gnfin(const float* __restrict__ gg, const float* __restrict__ gb)
{
    int c = threadIdx.x;                 // 0..127
    int bb = c >> 6, ch = c & 63, g = ch >> 3;
    const float N = 4915200.f;           // 8ch * 24 * 160 * 160
    float s  = g_gn[(bb*8+g)*2+0];
    float ss = g_gn[(bb*8+g)*2+1];
    float mu  = s / N;
    float var = ss / N - mu*mu;
    float A = gg[ch] * rsqrtf(var + 1e-5f);
    g_A[c] = A;
    g_B[c] = gb[ch] - mu * A;
}

// ---------------- f2: GN-affine + LeakyReLU (on the fly) + conv3d D (64->32),
//                  writes d_out = x + slice_features ----------------
__global__ void __launch_bounds__(256) k_f2(const float* __restrict__ x,
                                            const float* __restrict__ w,
                                            const float* __restrict__ b,
                                            float* __restrict__ out)
{
    __shared__ float ws[6144];           // [32oc][64ic][3t]
    __shared__ float As[128], Bs2[128];
    int tid = threadIdx.x;
    #pragma unroll 1
    for (int i = tid; i < 6144; i += 256) ws[i] = w[i];
    if (tid < 128){ As[tid]=g_A[tid]; Bs2[tid]=g_B[tid]; }
    __syncthreads();

    int n  = blockIdx.y; int bb = n / 24, d = n - bb*24;
    int lane = tid & 31, ocg = tid >> 5;         // oc = ocg*4..+3
    int hw0 = blockIdx.x * 256 + lane;

    float acc[4][8];
    #pragma unroll
    for (int j=0;j<4;j++){
        #pragma unroll
        for (int k=0;k<8;k++) acc[j][k]=0.f;
    }
    const float* sb = g_sf1 + bb*39321600;

    #pragma unroll 1
    for (int ic = 0; ic < 64; ic++) {
        float A = As[bb*64+ic], Bv = Bs2[bb*64+ic];
        float wr[4][3];
        #pragma unroll
        for (int j=0;j<4;j++){
            int oc = ocg*4+j;
            wr[j][0]=ws[oc*192+ic*3+0];
            wr[j][1]=ws[oc*192+ic*3+1];
            wr[j][2]=ws[oc*192+ic*3+2];
        }
        #pragma unroll
        for (int t=0;t<3;t++){
            int dd = d + t - 1;
            if (dd >= 0 && dd < 24){
                const float* sp = sb + ic*IMG + dd*HWSZ + hw0;
                #pragma unroll
                for (int k=0;k<8;k++){
                    float v = sp[k*32];
                    v = fmaf(A, v, Bv);
                    v = fmaxf(v, 0.2f*v);          // LeakyReLU(0.2)
                    #pragma unroll
                    for (int j=0;j<4;j++) acc[j][k] = fmaf(wr[j][t], v, acc[j][k]);
                }
            }
        }
    }

    #pragma unroll
    for (int j=0;j<4;j++){
        int oc = ocg*4+j;
        float bv = b[oc];
        int base = bb*BST + oc*IMG + d*HWSZ + hw0;
        #pragma unroll
        for (int k=0;k<8;k++)
            out[base + k*32] = __ldg(x + base + k*32) + acc[j][k] + bv;
    }
}

// ---------------- 3x3 conv (32->32) workhorse (FFMA2) ----------------
// MODE 0: precompute  u/r/o x-halves: out = conv(x)+bias -> g_pre[sel]
//         grid (100, 48)
// MODE 1: gates: z=0 -> u = sigmoid(conv_h(h)+Ux) -> g_u
//                z=1 -> rh = sigmoid(conv_h(h)+Rx)*h -> g_rh
//         grid (100, 4, 2)    n: 0,1 = fwd b0,b1 (d=s); 2,3 = bwd (d=23-s)
// MODE 2: cand+update: c=tanh(conv(rh)+Ox); hn=(1-u)h+uc; h'=hn; d_out+=hn
//         grid (100, 4)
template<int MODE>
__global__ void __launch_bounds__(256, 2)
k_conv(const float* __restrict__ in_x,
       const float* __restrict__ Wa,
       const float* __restrict__ Wb,
       const float* __restrict__ bias,
       float* __restrict__ outp,
       int sel, int ph, int s, int first)
{
    __shared__ float sIn[16*360];        // 16 ic chunk, 18 rows, stride 20
    __shared__ float sW[4608];           // 32 oc * 16 ic * 9

    int tid  = threadIdx.x;
    int tile = blockIdx.x;
    int tx = tile % 10, ty = tile / 10;
    int n = blockIdx.y;
    int z = blockIdx.z;

    int bb, d;
    if (MODE == 0){ bb = n / 24; d = n - bb*24; }
    else          { bb = n & 1;  d = (n < 2) ? s : 23 - s; }

    const float* in;
    int ibase, ics;
    if (MODE == 0){ in = in_x;    ibase = bb*BST + d*HWSZ; ics = IMG; }
    else if (MODE == 1){ in = g_h[ph]; ibase = n*819200; ics = HWSZ; }
    else { in = g_rh; ibase = n*819200; ics = HWSZ; }

    const float* Wp = (MODE == 1 && z == 1) ? Wb : Wa;

    int lane = tid & 31, ocg = tid >> 5;
    int sp_r = (lane >> 2) << 1;         // 0,2,...,14
    int sp_c = (lane & 3)  << 2;         // 0,4,8,12

    u64 acc2[2][2][4];                   // oc-pair x 2 rows x 4 cols
    #pragma unroll
    for (int jp=0;jp<2;jp++){
        #pragma unroll
        for (int r=0;r<2;r++){
            #pragma unroll
            for (int c=0;c<4;c++) acc2[jp][r][c]=0ull;
        }
    }

    bool skip = (MODE != 0) && (first != 0);   // h==0 -> conv contributes 0
    if (!skip) {
        #pragma unroll 1
        for (int cc = 0; cc < 2; cc++){
            int icc0 = cc * 16;
            if (cc) __syncthreads();
            // input chunk (with zero halo)
            #pragma unroll 1
            for (int idx = tid; idx < 16*324; idx += 256){
                int ic = idx / 324; int rem = idx - ic*324;
                int r = rem / 18;   int c2 = rem - r*18;
                int gy = ty*16 - 1 + r, gx = tx*16 - 1 + c2;
                float v = 0.f;
                if ((unsigned)gy < 160u && (unsigned)gx < 160u)
                    v = __ldg(in + ibase + (icc0+ic)*ics + gy*160 + gx);
                sIn[ic*360 + r*20 + c2] = v;
            }
            // weight chunk; global layout [32oc][64ic][3][3], base already at ic-part
            #pragma unroll 1
            for (int idx = tid; idx < 4608; idx += 256){
                int oc = idx / 144; int rem = idx - oc*144;
                int ic = rem / 9;   int k = rem - ic*9;
                sW[idx] = __ldg(Wp + oc*576 + (icc0+ic)*9 + k);
            }
            __syncthreads();

            #pragma unroll 1
            for (int ic = 0; ic < 16; ic++){
                u64 p2[4][6];
                #pragma unroll
                for (int r=0;r<4;r++){
                    #pragma unroll
                    for (int c2=0;c2<6;c2++){
                        float v = sIn[ic*360 + (sp_r+r)*20 + sp_c + c2];
                        p2[r][c2] = pack2(v, v);
                    }
                }
                #pragma unroll
                for (int jp=0;jp<2;jp++){
                    int oc0 = ocg*4 + 2*jp;
                    u64 w2[9];
                    #pragma unroll
                    for (int k=0;k<9;k++)
                        w2[k] = pack2(sW[oc0*144 + ic*9 + k],
                                      sW[(oc0+1)*144 + ic*9 + k]);
                    #pragma unroll
                    for (int dy=0;dy<3;dy++){
                        #pragma unroll
                        for (int dx=0;dx<3;dx++){
                            #pragma unroll
                            for (int ry=0;ry<2;ry++){
                                #pragma unroll
                                for (int cx=0;cx<4;cx++)
                                    acc2[jp][ry][cx] = fma2(w2[dy*3+dx],
                                                            p2[ry+dy][cx+dx],
                                                            acc2[jp][ry][cx]);
                            }
                        }
                    }
                }
            }
        }
    }

    // unpack pairs -> scalar accs
    float accs[4][2][4];
    #pragma unroll
    for (int jp=0;jp<2;jp++){
        #pragma unroll
        for (int ry=0;ry<2;ry++){
            #pragma unroll
            for (int cx=0;cx<4;cx++)
                unpack2(acc2[jp][ry][cx], accs[2*jp][ry][cx], accs[2*jp+1][ry][cx]);
        }
    }

    // ---------------- epilogue ----------------
    int oy0 = ty*16 + sp_r, ox0 = tx*16 + sp_c;
    #pragma unroll
    for (int j=0;j<4;j++){
        int oc = ocg*4 + j;
        #pragma unroll
        for (int ry=0;ry<2;ry++){
            int hw = (oy0+ry)*160 + ox0;
            #pragma unroll
            for (int cx=0;cx<4;cx++){
                float a = accs[j][ry][cx];
                int pidx = bb*BST + oc*IMG + d*HWSZ + hw + cx;  // [B,C,D,H,W] index
                int hidx = n*819200 + oc*HWSZ + hw + cx;        // h-buffer index
                if (MODE == 0){
                    g_pre[sel][pidx] = a + bias[oc];
                } else if (MODE == 1){
                    if (z == 0){
                        g_u[hidx] = sigm(a + g_pre[0][pidx]);
                    } else {
                        float r2 = sigm(a + g_pre[1][pidx]);
                        float hv = first ? 0.f : in[hidx];
                        g_rh[hidx] = r2 * hv;
                    }
                } else {
                    float c  = tanhf(a + g_pre[2][pidx]);
                    float u  = g_u[hidx];
                    float hp = first ? 0.f : g_h[ph][hidx];
                    float hn = (1.f - u)*hp + u*c;
                    g_h[ph^1][hidx] = hn;
                    outp[pidx] += hn;
                }
            }
        }
    }
}

// ---------------- host ----------------
extern "C" void kernel_launch(void* const* d_in, const int* in_sizes, int n_in,
                              void* d_out, int out_size)
{
    const float* x    = (const float*)d_in[0];
    const float* w_f1 = (const float*)d_in[1];
    const float* b_f1 = (const float*)d_in[2];
    const float* gn_g = (const float*)d_in[3];
    const float* gn_b = (const float*)d_in[4];
    const float* w_f2 = (const float*)d_in[5];
    const float* b_f2 = (const float*)d_in[6];
    const float* w_u  = (const float*)d_in[7];
    const float* b_u  = (const float*)d_in[8];
    const float* w_r  = (const float*)d_in[9];
    const float* b_r  = (const float*)d_in[10];
    const float* w_o  = (const float*)d_in[11];
    const float* b_o  = (const float*)d_in[12];
    float* out = (float*)d_out;

    dim3 gImg(100, 48);

    // slice_flow
    k_gz<<<1, 32>>>();
    k_f1<<<gImg, 256>>>(x, w_f1, b_f1);
    k_gnfin<<<1, 128>>>(gn_g, gn_b);
    k_f2<<<gImg, 256>>>(x, w_f2, b_f2, out);   // out = x + slice_features

    // GRU x-half precompute (shared by fwd and bwd)
    k_conv<0><<<gImg, 256>>>(x, w_u, nullptr, b_u, nullptr, 0, 0, 0, 0);
    k_conv<0><<<gImg, 256>>>(x, w_r, nullptr, b_r, nullptr, 1, 0, 0, 0);
    k_conv<0><<<gImg, 256>>>(x, w_o, nullptr, b_o, nullptr, 2, 0, 0, 0);

    // bidirectional scan: step s does fwd d=s (n=0,1) and bwd d=23-s (n=2,3)
    dim3 gUR(100, 4, 2), gO(100, 4);
    for (int s = 0; s < 24; s++){
        int ph = (s + 1) & 1;       // read g_h[ph], write g_h[ph^1]
        int first = (s == 0) ? 1 : 0;
        k_conv<1><<<gUR, 256>>>(nullptr, w_u + 288, w_r + 288, nullptr, nullptr,
                                0, ph, s, first);
        k_conv<2><<<gO, 256>>>(nullptr, w_o + 288, nullptr, nullptr, out,
                               0, ph, s, first);
    }
}

// round 7
// speedup vs baseline: 1.4243x; 1.4243x over previous
#include <cuda_runtime.h>
#include <math.h>

#define HWSZ 25600        // 160*160
#define IMG  614400       // 24*HWSZ  (per-channel size in [B,C,D,H,W])
#define BST  19660800     // 32*IMG   (per-batch stride for C=32 tensors)
#define HBUF 3276800      // 4 images * 32ch * HWSZ (fwd b0,b1 + bwd b0,b1)

// ---------------- scratch (device globals; no allocations) ----------------
__device__ float g_sf1[78643200];        // [2,64,24,160,160]  slice_flow mid
__device__ float g_pre[3][39321600];     // Ux, Rx, Ox  (x-layout [B,C,D,H,W])
__device__ float g_hist[2][39321600];    // fwd / bwd hidden history [B,C,D,H,W]
__device__ float g_h[2][HBUF];           // ping-pong hidden state, 4 images
__device__ float g_u[HBUF];              // update gate
__device__ float g_rh[HBUF];             // reset*h
__device__ float g_gn[32];               // [b][group][sum,sumsq]
__device__ float g_A[128];               // GN affine scale  [b][64]
__device__ float g_B[128];               // GN affine shift

__device__ __forceinline__ float sigm(float z){ return 1.0f/(1.0f+expf(-z)); }

// ---------------- zero the GN accumulator ----------------
__global__ void k_gz(){ if (threadIdx.x < 32) g_gn[threadIdx.x] = 0.f; }

// ---------------- f1: conv3d over D (32->64) + bias + GN partial sums ----------------
__global__ void __launch_bounds__(256) k_f1(const float* __restrict__ x,
                                            const float* __restrict__ w,
                                            const float* __restrict__ b)
{
    __shared__ float ws[6144];                       // [64oc][32ic][3t]
    int tid = threadIdx.x;
    #pragma unroll 1
    for (int i = tid; i < 6144; i += 256) ws[i] = w[i];
    __syncthreads();

    int n  = blockIdx.y; int bb = n / 24, d = n - bb*24;
    int lane = tid & 31, ocg = tid >> 5;             // ocg == GN group
    int hw0 = blockIdx.x * 256 + lane;

    float acc[8][8];
    #pragma unroll
    for (int j=0;j<8;j++){
        #pragma unroll
        for (int k=0;k<8;k++) acc[j][k]=0.f;
    }
    const float* xb = x + bb*BST;

    #pragma unroll 1
    for (int ic = 0; ic < 32; ic++) {
        float wr[8][3];
        #pragma unroll
        for (int j=0;j<8;j++){
            int oc = ocg*8+j;
            wr[j][0]=ws[oc*96+ic*3+0];
            wr[j][1]=ws[oc*96+ic*3+1];
            wr[j][2]=ws[oc*96+ic*3+2];
        }
        #pragma unroll
        for (int t=0;t<3;t++){
            int dd = d + t - 1;
            if (dd >= 0 && dd < 24){
                const float* xp = xb + ic*IMG + dd*HWSZ + hw0;
                #pragma unroll
                for (int k=0;k<8;k++){
                    float v = __ldg(xp + k*32);
                    #pragma unroll
                    for (int j=0;j<8;j++) acc[j][k] = fmaf(wr[j][t], v, acc[j][k]);
                }
            }
        }
    }

    float s=0.f, ss=0.f;
    #pragma unroll
    for (int j=0;j<8;j++){
        int oc = ocg*8+j;
        float bv = b[oc];
        float* op = g_sf1 + (bb*64+oc)*IMG + d*HWSZ + hw0;
        #pragma unroll
        for (int k=0;k<8;k++){
            float v = acc[j][k] + bv;
            op[k*32] = v;
            s += v; ss = fmaf(v,v,ss);
        }
    }
    #pragma unroll
    for (int o=16;o;o>>=1){
        s  += __shfl_xor_sync(0xffffffffu, s,  o);
        ss += __shfl_xor_sync(0xffffffffu, ss, o);
    }
    if (lane == 0){
        atomicAdd(&g_gn[(bb*8+ocg)*2+0], s);
        atomicAdd(&g_gn[(bb*8+ocg)*2+1], ss);
    }
}

// ---------------- GN finalize: per (b,channel) affine ----------------
__global__ void k_gnfin(const float* __restrict__ gg, const float* __restrict__ gb)
{
    int c = threadIdx.x;                 // 0..127
    int bb = c >> 6, ch = c & 63, g = ch >> 3;
    const float N = 4915200.f;           // 8ch * 24 * 160 * 160
    float s  = g_gn[(bb*8+g)*2+0];
    float ss = g_gn[(bb*8+g)*2+1];
    float mu  = s / N;
    float var = ss / N - mu*mu;
    float A = gg[ch] * rsqrtf(var + 1e-5f);
    g_A[c] = A;
    g_B[c] = gb[ch] - mu * A;
}

// ---------------- f2: GN-affine + LeakyReLU + conv3d D (64->32),
//                  writes d_out = x + slice_features ----------------
__global__ void __launch_bounds__(256) k_f2(const float* __restrict__ x,
                                            const float* __restrict__ w,
                                            const float* __restrict__ b,
                                            float* __restrict__ out)
{
    __shared__ float ws[6144];           // [32oc][64ic][3t]
    __shared__ float As[128], Bs2[128];
    int tid = threadIdx.x;
    #pragma unroll 1
    for (int i = tid; i < 6144; i += 256) ws[i] = w[i];
    if (tid < 128){ As[tid]=g_A[tid]; Bs2[tid]=g_B[tid]; }
    __syncthreads();

    int n  = blockIdx.y; int bb = n / 24, d = n - bb*24;
    int lane = tid & 31, ocg = tid >> 5;         // oc = ocg*4..+3
    int hw0 = blockIdx.x * 256 + lane;

    float acc[4][8];
    #pragma unroll
    for (int j=0;j<4;j++){
        #pragma unroll
        for (int k=0;k<8;k++) acc[j][k]=0.f;
    }
    const float* sb = g_sf1 + bb*39321600;

    #pragma unroll 1
    for (int ic = 0; ic < 64; ic++) {
        float A = As[bb*64+ic], Bv = Bs2[bb*64+ic];
        float wr[4][3];
        #pragma unroll
        for (int j=0;j<4;j++){
            int oc = ocg*4+j;
            wr[j][0]=ws[oc*192+ic*3+0];
            wr[j][1]=ws[oc*192+ic*3+1];
            wr[j][2]=ws[oc*192+ic*3+2];
        }
        #pragma unroll
        for (int t=0;t<3;t++){
            int dd = d + t - 1;
            if (dd >= 0 && dd < 24){
                const float* sp = sb + ic*IMG + dd*HWSZ + hw0;
                #pragma unroll
                for (int k=0;k<8;k++){
                    float v = sp[k*32];
                    v = fmaf(A, v, Bv);
                    v = fmaxf(v, 0.2f*v);          // LeakyReLU(0.2)
                    #pragma unroll
                    for (int j=0;j<4;j++) acc[j][k] = fmaf(wr[j][t], v, acc[j][k]);
                }
            }
        }
    }

    #pragma unroll
    for (int j=0;j<4;j++){
        int oc = ocg*4+j;
        float bv = b[oc];
        int base = bb*BST + oc*IMG + d*HWSZ + hw0;
        #pragma unroll
        for (int k=0;k<8;k++)
            out[base + k*32] = __ldg(x + base + k*32) + acc[j][k] + bv;
    }
}

// ---------------- 3x3 conv (32->32) workhorse (scalar FFMA) ----------------
// MODE 0: precompute  u/r/o x-halves: out = conv(x)+bias -> g_pre[sel]
// MODE 1: gates: z=0 -> u = sigmoid(conv_h(h)+Ux) -> g_u
//                z=1 -> rh = sigmoid(conv_h(h)+Rx)*h -> g_rh
// MODE 2: cand+update: c=tanh(conv(rh)+Ox); hn=(1-u)h+uc; h'=hn; g_hist=hn
template<int MODE>
__global__ void __launch_bounds__(256, 2)
k_conv(const float* __restrict__ in_x,
       const float* __restrict__ Wa,
       const float* __restrict__ Wb,
       const float* __restrict__ bias,
       float* __restrict__ outp,
       int sel, int ph, int s, int first)
{
    __shared__ float sIn[16*360];        // 16 ic chunk, 18 rows, stride 20
    __shared__ float sW[4608];           // 32 oc * 16 ic * 9

    int tid  = threadIdx.x;
    int tile = blockIdx.x;
    int tx = tile % 10, ty = tile / 10;
    int n = blockIdx.y;
    int z = blockIdx.z;

    int bb, d;
    if (MODE == 0){ bb = n / 24; d = n - bb*24; }
    else          { bb = n & 1;  d = (n < 2) ? s : 23 - s; }

    const float* in;
    int ibase, ics;
    if (MODE == 0){ in = in_x;    ibase = bb*BST + d*HWSZ; ics = IMG; }
    else if (MODE == 1){ in = g_h[ph]; ibase = n*819200; ics = HWSZ; }
    else { in = g_rh; ibase = n*819200; ics = HWSZ; }

    const float* Wp = (MODE == 1 && z == 1) ? Wb : Wa;

    int lane = tid & 31, ocg = tid >> 5;
    int sp_r = (lane >> 2) << 1;         // 0,2,...,14
    int sp_c = (lane & 3)  << 2;         // 0,4,8,12

    float acc[4][2][4];
    #pragma unroll
    for (int j=0;j<4;j++){
        #pragma unroll
        for (int r=0;r<2;r++){
            #pragma unroll
            for (int c=0;c<4;c++) acc[j][r][c]=0.f;
        }
    }

    bool skip = (MODE != 0) && (first != 0);   // h==0 -> conv contributes 0
    if (!skip) {
        #pragma unroll 1
        for (int cc = 0; cc < 2; cc++){
            int icc0 = cc * 16;
            if (cc) __syncthreads();
            // input chunk (with zero halo)
            #pragma unroll 1
            for (int idx = tid; idx < 16*324; idx += 256){
                int ic = idx / 324; int rem = idx - ic*324;
                int r = rem / 18;   int c2 = rem - r*18;
                int gy = ty*16 - 1 + r, gx = tx*16 - 1 + c2;
                float v = 0.f;
                if ((unsigned)gy < 160u && (unsigned)gx < 160u)
                    v = __ldg(in + ibase + (icc0+ic)*ics + gy*160 + gx);
                sIn[ic*360 + r*20 + c2] = v;
            }
            // weight chunk; global layout [32oc][64ic][3][3]
            #pragma unroll 1
            for (int idx = tid; idx < 4608; idx += 256){
                int oc = idx / 144; int rem = idx - oc*144;
                int ic = rem / 9;   int k = rem - ic*9;
                sW[idx] = __ldg(Wp + oc*576 + (icc0+ic)*9 + k);
            }
            __syncthreads();

            #pragma unroll 2
            for (int ic = 0; ic < 16; ic++){
                float p[4][6];
                #pragma unroll
                for (int r=0;r<4;r++){
                    #pragma unroll
                    for (int c2=0;c2<6;c2++)
                        p[r][c2] = sIn[ic*360 + (sp_r+r)*20 + sp_c + c2];
                }
                float wr[4][9];
                #pragma unroll
                for (int j=0;j<4;j++){
                    #pragma unroll
                    for (int k=0;k<9;k++)
                        wr[j][k] = sW[(ocg*4+j)*144 + ic*9 + k];
                }
                #pragma unroll
                for (int j=0;j<4;j++){
                    #pragma unroll
                    for (int dy=0;dy<3;dy++){
                        #pragma unroll
                        for (int dx=0;dx<3;dx++){
                            #pragma unroll
                            for (int ry=0;ry<2;ry++){
                                #pragma unroll
                                for (int cx=0;cx<4;cx++)
                                    acc[j][ry][cx] = fmaf(wr[j][dy*3+dx],
                                                          p[ry+dy][cx+dx],
                                                          acc[j][ry][cx]);
                            }
                        }
                    }
                }
            }
        }
    }

    // ---------------- epilogue ----------------
    int oy0 = ty*16 + sp_r, ox0 = tx*16 + sp_c;
    #pragma unroll
    for (int j=0;j<4;j++){
        int oc = ocg*4 + j;
        #pragma unroll
        for (int ry=0;ry<2;ry++){
            int hw = (oy0+ry)*160 + ox0;
            #pragma unroll
            for (int cx=0;cx<4;cx++){
                float a = acc[j][ry][cx];
                int pidx = bb*BST + oc*IMG + d*HWSZ + hw + cx;  // [B,C,D,H,W] index
                int hidx = n*819200 + oc*HWSZ + hw + cx;        // h-buffer index
                if (MODE == 0){
                    g_pre[sel][pidx] = a + bias[oc];
                } else if (MODE == 1){
                    if (z == 0){
                        g_u[hidx] = sigm(a + g_pre[0][pidx]);
                    } else {
                        float r2 = sigm(a + g_pre[1][pidx]);
                        float hv = first ? 0.f : in[hidx];
                        g_rh[hidx] = r2 * hv;
                    }
                } else {
                    float c  = tanhf(a + g_pre[2][pidx]);
                    float u  = g_u[hidx];
                    float hp = first ? 0.f : g_h[ph][hidx];
                    float hn = (1.f - u)*hp + u*c;
                    g_h[ph^1][hidx] = hn;
                    g_hist[n >= 2 ? 1 : 0][pidx] = hn;   // fwd / bwd history
                }
            }
        }
    }
}

// ---------------- merge: out += hist_f + hist_b (vectorized) ----------------
__global__ void __launch_bounds__(256) k_merge(float* __restrict__ out)
{
    int i = blockIdx.x * 256 + threadIdx.x;      // float4 index, 9830400 total
    float4 o = reinterpret_cast<float4*>(out)[i];
    float4 f = reinterpret_cast<const float4*>(g_hist[0])[i];
    float4 b = reinterpret_cast<const float4*>(g_hist[1])[i];
    o.x += f.x + b.x;  o.y += f.y + b.y;
    o.z += f.z + b.z;  o.w += f.w + b.w;
    reinterpret_cast<float4*>(out)[i] = o;
}

// ---------------- host ----------------
extern "C" void kernel_launch(void* const* d_in, const int* in_sizes, int n_in,
                              void* d_out, int out_size)
{
    const float* x    = (const float*)d_in[0];
    const float* w_f1 = (const float*)d_in[1];
    const float* b_f1 = (const float*)d_in[2];
    const float* gn_g = (const float*)d_in[3];
    const float* gn_b = (const float*)d_in[4];
    const float* w_f2 = (const float*)d_in[5];
    const float* b_f2 = (const float*)d_in[6];
    const float* w_u  = (const float*)d_in[7];
    const float* b_u  = (const float*)d_in[8];
    const float* w_r  = (const float*)d_in[9];
    const float* b_r  = (const float*)d_in[10];
    const float* w_o  = (const float*)d_in[11];
    const float* b_o  = (const float*)d_in[12];
    float* out = (float*)d_out;

    dim3 gImg(100, 48);

    // fork a side stream for the slice_flow chain (runs concurrently with
    // the GRU precompute + scan on the main stream)
    cudaStream_t s1;
    cudaStreamCreateWithFlags(&s1, cudaStreamNonBlocking);
    cudaEvent_t eFork, eJoin;
    cudaEventCreateWithFlags(&eFork, cudaEventDisableTiming);
    cudaEventCreateWithFlags(&eJoin, cudaEventDisableTiming);

    cudaEventRecord(eFork, 0);
    cudaStreamWaitEvent(s1, eFork, 0);

    // ---- slice_flow on s1: writes out = x + slice_features ----
    k_gz<<<1, 32, 0, s1>>>();
    k_f1<<<gImg, 256, 0, s1>>>(x, w_f1, b_f1);
    k_gnfin<<<1, 128, 0, s1>>>(gn_g, gn_b);
    k_f2<<<gImg, 256, 0, s1>>>(x, w_f2, b_f2, out);

    // ---- GRU on main stream ----
    k_conv<0><<<gImg, 256>>>(x, w_u, nullptr, b_u, nullptr, 0, 0, 0, 0);
    k_conv<0><<<gImg, 256>>>(x, w_r, nullptr, b_r, nullptr, 1, 0, 0, 0);
    k_conv<0><<<gImg, 256>>>(x, w_o, nullptr, b_o, nullptr, 2, 0, 0, 0);

    dim3 gUR(100, 4, 2), gO(100, 4);
    for (int s = 0; s < 24; s++){
        int ph = (s + 1) & 1;       // read g_h[ph], write g_h[ph^1]
        int first = (s == 0) ? 1 : 0;
        k_conv<1><<<gUR, 256>>>(nullptr, w_u + 288, w_r + 288, nullptr, nullptr,
                                0, ph, s, first);
        k_conv<2><<<gO, 256>>>(nullptr, w_o + 288, nullptr, nullptr, nullptr,
                               0, ph, s, first);
    }

    // join and merge: out += hist_f + hist_b
    cudaEventRecord(eJoin, s1);
    cudaStreamWaitEvent(0, eJoin, 0);
    k_merge<<<38400, 256>>>(out);
}

// round 8
// speedup vs baseline: 1.5603x; 1.0955x over previous
#include <cuda_runtime.h>
#include <math.h>
#include <stdint.h>

#define HWSZ 25600        // 160*160
#define IMG  614400       // 24*HWSZ  (per-channel size in [B,C,D,H,W])
#define BST  19660800     // 32*IMG   (per-batch stride for C=32 tensors)
#define HBUF 3276800      // 4 images * 32ch * HWSZ (fwd b0,b1 + bwd b0,b1)

// ---------------- scratch (device globals; no allocations) ----------------
__device__ float g_sf1[78643200];        // [2,64,24,160,160]  slice_flow mid
__device__ float g_pre[3][39321600];     // Ux, Rx, Ox  (x-layout [B,C,D,H,W])
__device__ float g_hist[2][39321600];    // fwd / bwd hidden history [B,C,D,H,W]
__device__ float g_h[2][HBUF];           // ping-pong hidden state, 4 images
__device__ float g_u[HBUF];              // update gate
__device__ float g_rh[HBUF];             // reset*h
__device__ float g_gn[32];               // [b][group][sum,sumsq]
__device__ float g_A[128];               // GN affine scale  [b][64]
__device__ float g_B[128];               // GN affine shift

__device__ __forceinline__ float sigm(float z){ return 1.0f/(1.0f+expf(-z)); }

__device__ __forceinline__ uint32_t tf32cvt(float f){
    uint32_t u; asm("cvt.rna.tf32.f32 %0, %1;" : "=r"(u) : "f"(f)); return u;
}

__device__ __forceinline__ void mma_tf32(float c[4], const uint32_t a[4],
                                         uint32_t b0, uint32_t b1){
    asm volatile(
        "mma.sync.aligned.m16n8k8.row.col.f32.tf32.tf32.f32 "
        "{%0,%1,%2,%3}, {%4,%5,%6,%7}, {%8,%9}, {%0,%1,%2,%3};"
        : "+f"(c[0]), "+f"(c[1]), "+f"(c[2]), "+f"(c[3])
        : "r"(a[0]), "r"(a[1]), "r"(a[2]), "r"(a[3]), "r"(b0), "r"(b1));
}

// ---------------- zero the GN accumulator ----------------
__global__ void k_gz(){ if (threadIdx.x < 32) g_gn[threadIdx.x] = 0.f; }

// ---------------- f1: conv3d over D (32->64) + bias + GN partial sums ----------------
__global__ void __launch_bounds__(256) k_f1(const float* __restrict__ x,
                                            const float* __restrict__ w,
                                            const float* __restrict__ b)
{
    __shared__ float ws[6144];                       // [64oc][32ic][3t]
    int tid = threadIdx.x;
    #pragma unroll 1
    for (int i = tid; i < 6144; i += 256) ws[i] = w[i];
    __syncthreads();

    int n  = blockIdx.y; int bb = n / 24, d = n - bb*24;
    int lane = tid & 31, ocg = tid >> 5;             // ocg == GN group
    int hw0 = blockIdx.x * 256 + lane;

    float acc[8][8];
    #pragma unroll
    for (int j=0;j<8;j++){
        #pragma unroll
        for (int k=0;k<8;k++) acc[j][k]=0.f;
    }
    const float* xb = x + bb*BST;

    #pragma unroll 1
    for (int ic = 0; ic < 32; ic++) {
        float wr[8][3];
        #pragma unroll
        for (int j=0;j<8;j++){
            int oc = ocg*8+j;
            wr[j][0]=ws[oc*96+ic*3+0];
            wr[j][1]=ws[oc*96+ic*3+1];
            wr[j][2]=ws[oc*96+ic*3+2];
        }
        #pragma unroll
        for (int t=0;t<3;t++){
            int dd = d + t - 1;
            if (dd >= 0 && dd < 24){
                const float* xp = xb + ic*IMG + dd*HWSZ + hw0;
                #pragma unroll
                for (int k=0;k<8;k++){
                    float v = __ldg(xp + k*32);
                    #pragma unroll
                    for (int j=0;j<8;j++) acc[j][k] = fmaf(wr[j][t], v, acc[j][k]);
                }
            }
        }
    }

    float s=0.f, ss=0.f;
    #pragma unroll
    for (int j=0;j<8;j++){
        int oc = ocg*8+j;
        float bv = b[oc];
        float* op = g_sf1 + (bb*64+oc)*IMG + d*HWSZ + hw0;
        #pragma unroll
        for (int k=0;k<8;k++){
            float v = acc[j][k] + bv;
            op[k*32] = v;
            s += v; ss = fmaf(v,v,ss);
        }
    }
    #pragma unroll
    for (int o=16;o;o>>=1){
        s  += __shfl_xor_sync(0xffffffffu, s,  o);
        ss += __shfl_xor_sync(0xffffffffu, ss, o);
    }
    if (lane == 0){
        atomicAdd(&g_gn[(bb*8+ocg)*2+0], s);
        atomicAdd(&g_gn[(bb*8+ocg)*2+1], ss);
    }
}

// ---------------- GN finalize ----------------
__global__ void k_gnfin(const float* __restrict__ gg, const float* __restrict__ gb)
{
    int c = threadIdx.x;                 // 0..127
    int bb = c >> 6, ch = c & 63, g = ch >> 3;
    const float N = 4915200.f;           // 8ch * 24 * 160 * 160
    float s  = g_gn[(bb*8+g)*2+0];
    float ss = g_gn[(bb*8+g)*2+1];
    float mu  = s / N;
    float var = ss / N - mu*mu;
    float A = gg[ch] * rsqrtf(var + 1e-5f);
    g_A[c] = A;
    g_B[c] = gb[ch] - mu * A;
}

// ---------------- f2: GN-affine + LeakyReLU + conv3d D (64->32) ----------------
__global__ void __launch_bounds__(256) k_f2(const float* __restrict__ x,
                                            const float* __restrict__ w,
                                            const float* __restrict__ b,
                                            float* __restrict__ out)
{
    __shared__ float ws[6144];           // [32oc][64ic][3t]
    __shared__ float As[128], Bs2[128];
    int tid = threadIdx.x;
    #pragma unroll 1
    for (int i = tid; i < 6144; i += 256) ws[i] = w[i];
    if (tid < 128){ As[tid]=g_A[tid]; Bs2[tid]=g_B[tid]; }
    __syncthreads();

    int n  = blockIdx.y; int bb = n / 24, d = n - bb*24;
    int lane = tid & 31, ocg = tid >> 5;         // oc = ocg*4..+3
    int hw0 = blockIdx.x * 256 + lane;

    float acc[4][8];
    #pragma unroll
    for (int j=0;j<4;j++){
        #pragma unroll
        for (int k=0;k<8;k++) acc[j][k]=0.f;
    }
    const float* sb = g_sf1 + bb*39321600;

    #pragma unroll 1
    for (int ic = 0; ic < 64; ic++) {
        float A = As[bb*64+ic], Bv = Bs2[bb*64+ic];
        float wr[4][3];
        #pragma unroll
        for (int j=0;j<4;j++){
            int oc = ocg*4+j;
            wr[j][0]=ws[oc*192+ic*3+0];
            wr[j][1]=ws[oc*192+ic*3+1];
            wr[j][2]=ws[oc*192+ic*3+2];
        }
        #pragma unroll
        for (int t=0;t<3;t++){
            int dd = d + t - 1;
            if (dd >= 0 && dd < 24){
                const float* sp = sb + ic*IMG + dd*HWSZ + hw0;
                #pragma unroll
                for (int k=0;k<8;k++){
                    float v = sp[k*32];
                    v = fmaf(A, v, Bv);
                    v = fmaxf(v, 0.2f*v);          // LeakyReLU(0.2)
                    #pragma unroll
                    for (int j=0;j<4;j++) acc[j][k] = fmaf(wr[j][t], v, acc[j][k]);
                }
            }
        }
    }

    #pragma unroll
    for (int j=0;j<4;j++){
        int oc = ocg*4+j;
        float bv = b[oc];
        int base = bb*BST + oc*IMG + d*HWSZ + hw0;
        #pragma unroll
        for (int k=0;k<8;k++)
            out[base + k*32] = __ldg(x + base + k*32) + acc[j][k] + bv;
    }
}

// ---------------- 3x3 conv (32->32) via tf32 mma.sync ----------------
// Implicit GEMM: M = 16 pixels (one image row per m-tile, 2 m-tiles/warp),
// N = 32 oc (4 n-tiles of 8), K = 288 (9 taps x 32 ic; chunk = fixed tap,
// 8 contiguous ic). Accumulate fp32; inputs rounded to tf32 at smem fill.
// MODE 0: g_pre[sel] = conv(x)+bias               grid (100, 48)
// MODE 1: z=0: g_u = sigm(conv(h)+Ux)
//         z=1: g_rh = sigm(conv(h)+Rx)*h          grid (100, 4, 2)
// MODE 2: c=tanh(conv(rh)+Ox); h'=(1-u)h+uc; hist grid (100, 4)
template<int MODE>
__global__ void __launch_bounds__(256, 2)
k_conv(const float* __restrict__ in_x,
       const float* __restrict__ Wa,
       const float* __restrict__ Wb,
       const float* __restrict__ bias,
       int sel, int ph, int s, int first)
{
    __shared__ uint32_t sIn[16*360];     // [16 ic][18 rows][stride 20]  tf32 bits
    __shared__ uint32_t sW[9*32*18];     // [9 kk][32 oc][18 pad]        tf32 bits

    int tid  = threadIdx.x;
    int tile = blockIdx.x;
    int tx = tile % 10, ty = tile / 10;
    int n = blockIdx.y;
    int z = blockIdx.z;

    int bb, d;
    if (MODE == 0){ bb = n / 24; d = n - bb*24; }
    else          { bb = n & 1;  d = (n < 2) ? s : 23 - s; }

    const float* in;
    int ibase, ics;
    if (MODE == 0){ in = in_x;    ibase = bb*BST + d*HWSZ; ics = IMG; }
    else if (MODE == 1){ in = g_h[ph]; ibase = n*819200; ics = HWSZ; }
    else { in = g_rh; ibase = n*819200; ics = HWSZ; }

    const float* Wp = (MODE == 1 && z == 1) ? Wb : Wa;

    int lane = tid & 31;
    int w2   = (tid >> 5) * 2;           // this warp's two image rows (in-tile)
    int lq   = lane >> 2;                // 0..7
    int lr   = lane & 3;                 // 0..3

    float c[2][4][4];                    // [m-tile][n-tile][c-reg]
    #pragma unroll
    for (int mt=0;mt<2;mt++)
        #pragma unroll
        for (int nt=0;nt<4;nt++)
            #pragma unroll
            for (int k=0;k<4;k++) c[mt][nt][k]=0.f;

    bool skip = (MODE != 0) && (first != 0);   // h==0 -> conv contributes 0
    if (!skip) {
        #pragma unroll 1
        for (int cc = 0; cc < 2; cc++){
            int icc0 = cc * 16;
            if (cc) __syncthreads();
            // input chunk (with zero halo), tf32-rounded
            #pragma unroll 1
            for (int idx = tid; idx < 16*324; idx += 256){
                int ic = idx / 324; int rem = idx - ic*324;
                int r = rem / 18;   int c2 = rem - r*18;
                int gy = ty*16 - 1 + r, gx = tx*16 - 1 + c2;
                float v = 0.f;
                if ((unsigned)gy < 160u && (unsigned)gx < 160u)
                    v = __ldg(in + ibase + (icc0+ic)*ics + gy*160 + gx);
                sIn[ic*360 + r*20 + c2] = tf32cvt(v);
            }
            // weights: global [32oc][64ic][3][3] -> sW[kk][oc][18]
            #pragma unroll 1
            for (int idx = tid; idx < 4608; idx += 256){
                int oc = idx / 144; int rem = idx - oc*144;
                int ic = rem / 9;   int kk = rem - ic*9;
                sW[kk*576 + oc*18 + ic] =
                    tf32cvt(__ldg(Wp + oc*576 + (icc0+ic)*9 + kk));
            }
            __syncthreads();

            #pragma unroll
            for (int kk = 0; kk < 9; kk++){
                int dy = kk / 3, dx = kk - dy*3;
                #pragma unroll
                for (int h = 0; h < 2; h++){
                    uint32_t a[2][4];
                    int abase0 = (h*8 + lr)*360 + (w2 + dy)*20 + lq + dx;
                    #pragma unroll
                    for (int mt=0;mt<2;mt++){
                        int ab = abase0 + mt*20;
                        a[mt][0] = sIn[ab];
                        a[mt][1] = sIn[ab + 8];
                        a[mt][2] = sIn[ab + 4*360];
                        a[mt][3] = sIn[ab + 4*360 + 8];
                    }
                    #pragma unroll
                    for (int nt=0;nt<4;nt++){
                        int bidx = kk*576 + (nt*8 + lq)*18 + h*8 + lr;
                        uint32_t b0 = sW[bidx], b1 = sW[bidx + 4];
                        mma_tf32(c[0][nt], a[0], b0, b1);
                        mma_tf32(c[1][nt], a[1], b0, b1);
                    }
                }
            }
        }
    }

    // ---------------- epilogue ----------------
    // C layout: c0:(x=lq, oc=nt*8+2*lr) c1:(oc+1) c2:(x=lq+8) c3:(x+8,oc+1)
    #pragma unroll
    for (int mt=0;mt<2;mt++){
        int oy = ty*16 + w2 + mt;
        #pragma unroll
        for (int nt=0;nt<4;nt++){
            #pragma unroll
            for (int cr=0;cr<4;cr++){
                int x  = lq + ((cr >> 1) << 3);
                int oc = nt*8 + lr*2 + (cr & 1);
                int ox = tx*16 + x;
                int hw = oy*160 + ox;
                float a = c[mt][nt][cr];
                int pidx = bb*BST + oc*IMG + d*HWSZ + hw;   // [B,C,D,H,W]
                int hidx = n*819200 + oc*HWSZ + hw;         // h-buffer
                if (MODE == 0){
                    g_pre[sel][pidx] = a + __ldg(bias + oc);
                } else if (MODE == 1){
                    if (z == 0){
                        g_u[hidx] = sigm(a + g_pre[0][pidx]);
                    } else {
                        float r2 = sigm(a + g_pre[1][pidx]);
                        float hv = first ? 0.f : in[hidx];
                        g_rh[hidx] = r2 * hv;
                    }
                } else {
                    float cd = tanhf(a + g_pre[2][pidx]);
                    float u  = g_u[hidx];
                    float hp = first ? 0.f : g_h[ph][hidx];
                    float hn = (1.f - u)*hp + u*cd;
                    g_h[ph^1][hidx] = hn;
                    g_hist[n >= 2 ? 1 : 0][pidx] = hn;
                }
            }
        }
    }
}

// ---------------- merge: out += hist_f + hist_b (vectorized) ----------------
__global__ void __launch_bounds__(256) k_merge(float* __restrict__ out)
{
    int i = blockIdx.x * 256 + threadIdx.x;      // float4 index, 9830400 total
    float4 o = reinterpret_cast<float4*>(out)[i];
    float4 f = reinterpret_cast<const float4*>(g_hist[0])[i];
    float4 b = reinterpret_cast<const float4*>(g_hist[1])[i];
    o.x += f.x + b.x;  o.y += f.y + b.y;
    o.z += f.z + b.z;  o.w += f.w + b.w;
    reinterpret_cast<float4*>(out)[i] = o;
}

// ---------------- host ----------------
extern "C" void kernel_launch(void* const* d_in, const int* in_sizes, int n_in,
                              void* d_out, int out_size)
{
    const float* x    = (const float*)d_in[0];
    const float* w_f1 = (const float*)d_in[1];
    const float* b_f1 = (const float*)d_in[2];
    const float* gn_g = (const float*)d_in[3];
    const float* gn_b = (const float*)d_in[4];
    const float* w_f2 = (const float*)d_in[5];
    const float* b_f2 = (const float*)d_in[6];
    const float* w_u  = (const float*)d_in[7];
    const float* b_u  = (const float*)d_in[8];
    const float* w_r  = (const float*)d_in[9];
    const float* b_r  = (const float*)d_in[10];
    const float* w_o  = (const float*)d_in[11];
    const float* b_o  = (const float*)d_in[12];
    float* out = (float*)d_out;

    dim3 gImg(100, 48);

    // fork a side stream for the fp32 slice_flow chain (concurrent with GRU)
    cudaStream_t s1;
    cudaStreamCreateWithFlags(&s1, cudaStreamNonBlocking);
    cudaEvent_t eFork, eJoin;
    cudaEventCreateWithFlags(&eFork, cudaEventDisableTiming);
    cudaEventCreateWithFlags(&eJoin, cudaEventDisableTiming);

    cudaEventRecord(eFork, 0);
    cudaStreamWaitEvent(s1, eFork, 0);

    // ---- slice_flow on s1: writes out = x + slice_features ----
    k_gz<<<1, 32, 0, s1>>>();
    k_f1<<<gImg, 256, 0, s1>>>(x, w_f1, b_f1);
    k_gnfin<<<1, 128, 0, s1>>>(gn_g, gn_b);
    k_f2<<<gImg, 256, 0, s1>>>(x, w_f2, b_f2, out);

    // ---- GRU on main stream (tf32 mma) ----
    k_conv<0><<<gImg, 256>>>(x, w_u, nullptr, b_u, 0, 0, 0, 0);
    k_conv<0><<<gImg, 256>>>(x, w_r, nullptr, b_r, 1, 0, 0, 0);
    k_conv<0><<<gImg, 256>>>(x, w_o, nullptr, b_o, 2, 0, 0, 0);

    dim3 gUR(100, 4, 2), gO(100, 4);
    for (int s = 0; s < 24; s++){
        int ph = (s + 1) & 1;       // read g_h[ph], write g_h[ph^1]
        int first = (s == 0) ? 1 : 0;
        k_conv<1><<<gUR, 256>>>(nullptr, w_u + 288, w_r + 288, nullptr,
                                0, ph, s, first);
        k_conv<2><<<gO, 256>>>(nullptr, w_o + 288, nullptr, nullptr,
                               0, ph, s, first);
    }

    // join and merge: out += hist_f + hist_b
    cudaEventRecord(eJoin, s1);
    cudaStreamWaitEvent(0, eJoin, 0);
    k_merge<<<38400, 256>>>(out);
}